// round 12
// baseline (speedup 1.0000x reference)
// MinervaEnhancedLoss — R12 resubmit of the R11 half-batch build (hash touch
// only; R11 never executed — broker container died pre-compile, 4th flake).
// Half-batch CTAs (1024 x 256): 6.9 units/SM (7v6 imbalance ~8% vs 33% for
// one-batch CTAs), 4 CTAs/SM resident, exact cross-half merge.
#include <cuda_runtime.h>
#include <cstdint>

#define B_    512
#define NH    1024          // half-CTAs (2 per batch)
#define C_    10
#define HW_   4096          // 64*64
#define HHW_  2048          // pixels per half
#define W_    64
#define SRN   128
#define THREADS 256
#define NWARPS  8
#define BITWORDS 313        // ceil(10000/32)

// ---------------- global state (self-resetting across graph replays) --------
__device__ float         a_focal[NH];    // raw (unweighted) focal sum per half
__device__ float         a_creat[B_];    // sigmoid sum (written by half 0)
__device__ unsigned int  a_eq[NH];       // eq count per half
__device__ unsigned int  a_cp[NH];       // copy-eq count per half
__device__ unsigned int  a_mask[NH];     // target-color presence per half
__device__ unsigned int  a_un[B_];       // unique 2x2 codes per batch (merged)
__device__ unsigned int  a_bm[NH][BITWORDS]; // per-half diversity bitmaps
__device__ unsigned int  a_arrive[B_];   // per-batch arrival ticket (resets to 0)
__device__ unsigned int  g_count = 0;    // completion counter (resets to 0)

// ---------------- helpers ---------------------------------------------------
__device__ __forceinline__ float warpSumF(float v) {
#pragma unroll
    for (int o = 16; o; o >>= 1) v += __shfl_down_sync(0xffffffffu, v, o);
    return v;
}
__device__ __forceinline__ double warpSumD(double v) {
#pragma unroll
    for (int o = 16; o; o >>= 1) v += __shfl_down_sync(0xffffffffu, v, o);
    return v;
}
__device__ __forceinline__ unsigned warpSumU(unsigned v) {
#pragma unroll
    for (int o = 16; o; o >>= 1) v += __shfl_down_sync(0xffffffffu, v, o);
    return v;
}
__device__ __forceinline__ unsigned warpOrU(unsigned v) {
#pragma unroll
    for (int o = 16; o; o >>= 1) v |= __shfl_down_sync(0xffffffffu, v, o);
    return v;
}

// Online logsumexp + argmax, single-MUFU recurrence (R9-proven).
__device__ __forceinline__ void upd(float& m, float& s, int& bi, float& vt,
                                    float v, int c, int t) {
    float e  = __expf(-fabsf(v - m));
    bool  gt = (v > m);
    s  = gt ? __fmaf_rn(s, e, 1.0f) : (s + e);
    if (gt) bi = c;                 // strict > keeps FIRST max (jnp.argmax)
    m  = fmaxf(m, v);
    if (c == t) vt = v;
}

// ---------------- single fused kernel ---------------------------------------
__global__ __launch_bounds__(THREADS, 4)
void minerva_half_kernel_r12(const float* __restrict__ pred,
                             const int*   __restrict__ targets,
                             const int*   __restrict__ inputs,
                             const float* __restrict__ sr,
                             float*       __restrict__ out) {
    __shared__ unsigned char s_pred[HHW_];     // this half's pred_idx (local rows 0..31)
    __shared__ unsigned char s_row31[W_];      // global row 31 argmax (half 1 only)
    __shared__ unsigned int  s_bitmap[BITWORDS];
    __shared__ float         s_f[NWARPS];
    __shared__ double        s_d[NWARPS];
    __shared__ double        s_d2[NWARPS];
    __shared__ unsigned int  s_u[NWARPS];
    __shared__ unsigned int  s_u2[NWARPS];
    __shared__ unsigned int  s_u3[NWARPS];
    __shared__ unsigned int  s_u4[NWARPS];
    __shared__ unsigned int  s_present;
    __shared__ int           s_second;
    __shared__ int           s_last;

    const int bid  = blockIdx.x;
    const int b    = bid >> 1;          // batch
    const int half = bid & 1;           // 0: rows 0..31, 1: rows 32..63
    const int tid  = threadIdx.x;
    const int lane = tid & 31;
    const int wid  = tid >> 5;

    if (tid == 0) s_present = 0u;
    __syncthreads();

    const float4* pb4 = reinterpret_cast<const float4*>(pred    + (size_t)b * C_ * HW_);
    const int4*   tb4 = reinterpret_cast<const int4*>(targets + (size_t)b * HW_);
    const int4*   ib4 = reinterpret_cast<const int4*>(inputs  + (size_t)b * HW_);

    float    focal_local = 0.f;
    unsigned eq_local = 0u, cp_local = 0u, pmask = 0u;

#pragma unroll
    for (int i = 0; i < 2; i++) {
        const int gl = tid + i * THREADS;        // local float4 group (0..511)
        const int gg = half * (HHW_ / 4) + gl;   // group within batch
        float4 v0 = pb4[gg];                      // channel 0
        int4   tt = tb4[gg];
        int4   ii = ib4[gg];

        float m[4]  = {v0.x, v0.y, v0.z, v0.w};
        float s[4]  = {1.f, 1.f, 1.f, 1.f};
        float vt[4] = {v0.x, v0.y, v0.z, v0.w};
        int   bi[4] = {0, 0, 0, 0};
        int   t[4]  = {tt.x, tt.y, tt.z, tt.w};
        int   ip[4] = {ii.x, ii.y, ii.z, ii.w};

#pragma unroll
        for (int c = 1; c < C_; c++) {
            float4 v = pb4[c * (HW_ / 4) + gg];
            float va[4] = {v.x, v.y, v.z, v.w};
#pragma unroll
            for (int j = 0; j < 4; j++) upd(m[j], s[j], bi[j], vt[j], va[j], c, t[j]);
        }

        unsigned char pj[4];
#pragma unroll
        for (int j = 0; j < 4; j++) {
            float ce = m[j] + __logf(s[j]) - vt[j];
            float pt = __expf(-ce);
            float om = 1.f - pt;
            focal_local += om * om * ce;
            eq_local += (bi[j] == t[j]);
            cp_local += (bi[j] == ip[j]);
            pmask |= 1u << t[j];
            pj[j] = (unsigned char)bi[j];
        }
        reinterpret_cast<uchar4*>(s_pred)[gl] = make_uchar4(pj[0], pj[1], pj[2], pj[3]);
    }

    pmask = warpOrU(pmask);
    if (lane == 0) atomicOr(&s_present, pmask);

    // creativity: half 0 handles all 128 sr values for this batch
    float creat_local = 0.f;
    if (half == 0 && tid < SRN) {
        float x = sr[(size_t)b * SRN + tid];
        creat_local = __fdividef(1.f, 1.f + __expf(-x));
    }

    // ---- block reductions ----
    float fsum   = warpSumF(focal_local);
    float crsum  = warpSumF(creat_local);
    unsigned es  = warpSumU(eq_local);
    unsigned cs  = warpSumU(cp_local);
    if (lane == 0) { s_f[wid] = fsum; s_d[wid] = (double)crsum; s_u[wid] = es; s_u2[wid] = cs; }

    // ---- half 1: recompute global row 31 argmax (needed for its first window row)
    if (half == 1 && tid < 16) {
        const int gg31 = (31 * W_) / 4 + tid;   // row 31, group tid
        float4 v0 = pb4[gg31];
        float m[4]  = {v0.x, v0.y, v0.z, v0.w};
        int   bi[4] = {0, 0, 0, 0};
#pragma unroll
        for (int c = 1; c < C_; c++) {
            float4 v = pb4[c * (HW_ / 4) + gg31];
            float va[4] = {v.x, v.y, v.z, v.w};
#pragma unroll
            for (int j = 0; j < 4; j++) {
                if (va[j] > m[j]) { m[j] = va[j]; bi[j] = c; }
            }
        }
        reinterpret_cast<uchar4*>(s_row31)[tid] =
            make_uchar4((unsigned char)bi[0], (unsigned char)bi[1],
                        (unsigned char)bi[2], (unsigned char)bi[3]);
    }

    for (int k = tid; k < BITWORDS; k += THREADS) s_bitmap[k] = 0u;
    __syncthreads();   // orders s_pred/s_row31/bitmap-zero/reduction stores

    // ---- diversity windows ----
    // half 0: window rows 0..30 (31*63); half 1: window rows 31..62 (32*63)
    const int nwin = (half == 0) ? 31 * 63 : 32 * 63;
    for (int idx = tid; idx < nwin; idx += THREADS) {
        int wr = idx / 63, w = idx - wr * 63;
        int p00, p01, p10, p11;
        if (half == 0) {
            int base = wr * W_ + w;
            p00 = s_pred[base];       p01 = s_pred[base + 1];
            p10 = s_pred[base + W_];  p11 = s_pred[base + W_ + 1];
        } else if (wr == 0) {         // global rows 31->32 (row 32 = local row 0)
            p00 = s_row31[w];         p01 = s_row31[w + 1];
            p10 = s_pred[w];          p11 = s_pred[w + 1];
        } else {
            int base = (wr - 1) * W_ + w;
            p00 = s_pred[base];       p01 = s_pred[base + 1];
            p10 = s_pred[base + W_];  p11 = s_pred[base + W_ + 1];
        }
        int code = p00 * 1000 + p01 * 100 + p10 * 10 + p11;
        atomicOr(&s_bitmap[code >> 5], 1u << (code & 31));
    }
    __syncthreads();

    // ---- publish per-half results + bitmap ----
    if (tid == 0) {
        float ft = 0.f; double cr = 0.0;
        unsigned eu = 0u, cu = 0u;
        for (int k = 0; k < NWARPS; k++) { ft += s_f[k]; cr += s_d[k]; eu += s_u[k]; cu += s_u2[k]; }
        a_focal[bid] = ft;            // raw; weight applied at finalize
        a_eq[bid]    = eu;
        a_cp[bid]    = cu;
        a_mask[bid]  = s_present;
        if (half == 0) a_creat[b] = (float)cr;
    }
    for (int k = tid; k < BITWORDS; k += THREADS) a_bm[bid][k] = s_bitmap[k];
    __threadfence();                  // every thread fences its own global stores
    __syncthreads();

    // ---- per-batch second-arriver merges the two bitmaps ----
    if (tid == 0) {
        unsigned arr = atomicAdd(&a_arrive[b], 1u);
        s_second = (arr == 1u);
    }
    __syncthreads();
    if (s_second) {                   // block-uniform (shared flag)
        __threadfence();              // partner's fenced stores visible (ticket observed)
        const int partner = bid ^ 1;
        unsigned cnt = 0u;
        for (int k = tid; k < BITWORDS; k += THREADS)
            cnt += __popc(s_bitmap[k] | a_bm[partner][k]);
        cnt = warpSumU(cnt);
        if (lane == 0) s_u3[wid] = cnt;
        __syncthreads();
        if (tid == 0) {
            unsigned tot = 0u;
            for (int k = 0; k < NWARPS; k++) tot += s_u3[k];
            a_un[b] = tot;
            a_arrive[b] = 0u;         // reset for next graph replay
        }
    }

    // ---- completion ticket; last of 1024 finalizes ----
    if (tid == 0) {
        __threadfence();
        unsigned prev = atomicAdd(&g_count, 1u);
        s_last = (prev == (unsigned)(NH - 1));
    }
    __syncthreads();
    if (!s_last) return;

    if (tid == 0) g_count = 0;        // reset for next graph replay

    double f = 0.0, cr = 0.0;
    unsigned eq = 0u, st = 0u, cp = 0u, un = 0u;
    for (int k = tid; k < B_; k += THREADS) {
        unsigned msk = a_mask[2 * k] | a_mask[2 * k + 1];
        float    w   = (__popc(msk) > 3) ? 1.2f : 1.0f;
        f  += (double)((a_focal[2 * k] + a_focal[2 * k + 1]) * w);
        cr += (double)a_creat[k];
        unsigned e = a_eq[2 * k] + a_eq[2 * k + 1];
        eq += e;
        st += (e == HW_);
        cp += ((a_cp[2 * k] + a_cp[2 * k + 1]) == HW_);
        un += a_un[k];
    }
    f  = warpSumD(f);
    cr = warpSumD(cr);
    eq = warpSumU(eq);
    st = warpSumU(st);
    cp = warpSumU(cp);
    un = warpSumU(un);
    if (lane == 0) {
        s_d[wid] = f; s_d2[wid] = cr;
        s_u[wid] = eq; s_u2[wid] = cp; s_u3[wid] = un; s_u4[wid] = st;
    }
    __syncthreads();

    if (tid == 0) {
        double F = 0.0, CR = 0.0;
        unsigned EQ = 0u, ST = 0u, CP = 0u, UN = 0u;
        for (int k = 0; k < NWARPS; k++) {
            F += s_d[k]; CR += s_d2[k];
            EQ += s_u[k]; ST += s_u4[k]; CP += s_u2[k]; UN += s_u3[k];
        }

        const double NPIX = (double)B_ * (double)HW_;
        const double NWIN_T = 3969.0;
        double focal       = F / NPIX;
        double iou_mean    = (double)EQ / NPIX;
        double exact_count = 0.2 * (double)ST + 0.8 * ((double)EQ / (double)HW_);
        double comb_mean   = exact_count / (double)B_;
        double exact_bonus = fmax(-comb_mean * 5.0, -3.0);
        double transform_p = ((double)CP / (double)B_) * 0.2;
        double creat       = (CR / ((double)B_ * SRN)) * 0.15;
        double divers      = ((double)UN / NWIN_T) / (double)B_ * 0.02;
        double grid_bonus  = comb_mean * 0.05;   // grid_size_factor == 1

        double total = focal + transform_p + exact_bonus - creat - divers - grid_bonus;
        if (isnan(total) || isinf(total)) total = fmin(focal, 10.0);

        out[0] = (float)total;
        out[1] = (float)focal;
        out[2] = (float)transform_p;
        out[3] = (float)exact_bonus;
        out[4] = (float)exact_count;
        out[5] = (float)exact_count;
        out[6] = (float)iou_mean;
        out[7] = (float)creat;
        out[8] = (float)divers;
        out[9] = (float)grid_bonus;
    }
}

// ---------------- launch -----------------------------------------------------
extern "C" void kernel_launch(void* const* d_in, const int* in_sizes, int n_in,
                              void* d_out, int out_size) {
    const float* pred    = (const float*)d_in[0];
    const int*   targets = (const int*)d_in[1];
    const int*   inputs  = (const int*)d_in[2];
    const float* sr      = (const float*)d_in[3];
    float*       out     = (float*)d_out;

    minerva_half_kernel_r12<<<NH, THREADS>>>(pred, targets, inputs, sr, out);
}

// round 15
// speedup vs baseline: 1.0377x; 1.0377x over previous
// MinervaEnhancedLoss — R15: third submission of the off-chain-SEL build.
// (R13, R14 both died in the broker pre-compile; 6th infra flake overall.
//  Hash touched again; semantics identical to R13/R14.)
// Base: R9 (512x256, lb(256,4), 32.8us). Change under test: s-recurrence
//   s = fma(s, gt?e:1, gt?1:e)  — bit-identical math, serial step 8->4 cyc.
#include <cuda_runtime.h>
#include <cstdint>

// Problem constants
#define B_    512
#define C_    10
#define HW_   4096          // 64*64
#define W_    64
#define NWIN  3969          // 63*63
#define SRN   128           // strategic_reasoning row length
#define THREADS 256
#define NWARPS  8
#define BITWORDS 313        // ceil(10000/32)

// ---------------- per-block result arrays (written every run; no init) ------
__device__ float         a_focal[B_];   // weighted focal sum per batch
__device__ float         a_creat[B_];   // sigmoid sum per batch
__device__ unsigned int  a_eq[B_];      // eq count per batch
__device__ unsigned int  a_cp[B_];      // copy-eq count per batch
__device__ unsigned int  a_un[B_];      // unique 2x2 codes per batch
__device__ unsigned int  g_count = 0;   // completion counter (reset by last block)

// ---------------- helpers ---------------------------------------------------
__device__ __forceinline__ float warpSumF(float v) {
#pragma unroll
    for (int o = 16; o; o >>= 1) v += __shfl_down_sync(0xffffffffu, v, o);
    return v;
}
__device__ __forceinline__ double warpSumD(double v) {
#pragma unroll
    for (int o = 16; o; o >>= 1) v += __shfl_down_sync(0xffffffffu, v, o);
    return v;
}
__device__ __forceinline__ unsigned warpSumU(unsigned v) {
#pragma unroll
    for (int o = 16; o; o >>= 1) v += __shfl_down_sync(0xffffffffu, v, o);
    return v;
}
__device__ __forceinline__ unsigned warpOrU(unsigned v) {
#pragma unroll
    for (int o = 16; o; o >>= 1) v |= __shfl_down_sync(0xffffffffu, v, o);
    return v;
}

// Online logsumexp + argmax, single-MUFU + single-FFMA-chain form.
// e = exp(-|v-m|); exactly one softmax branch multiplies s by e:
//   gt:  s_new = fma(s, e, 1)      (identical to prior branchy form)
//   !gt: s_new = fma(s, 1, e)      (== s+e with one rounding, same as FADD)
// The SELs producing (e1,e2) depend only on e/gt — OFF the s-chain — so the
// serial recurrence step is a single 4-cycle FFMA.
__device__ __forceinline__ void upd(float& m, float& s, int& bi, float& vt,
                                    float v, int c, int t) {
    float e  = __expf(-fabsf(v - m));
    bool  gt = (v > m);
    float e1 = gt ? e    : 1.0f;
    float e2 = gt ? 1.0f : e;
    s  = __fmaf_rn(s, e1, e2);
    if (gt) bi = c;                 // strict > keeps FIRST max (jnp.argmax)
    m  = fmaxf(m, v);
    if (c == t) vt = v;
}

// ---------------- single fused kernel ---------------------------------------
__global__ __launch_bounds__(THREADS, 4)
void minerva_fused_kernel_r15(const float* __restrict__ pred,
                              const int*   __restrict__ targets,
                              const int*   __restrict__ inputs,
                              const float* __restrict__ sr,
                              float*       __restrict__ out) {
    __shared__ unsigned char s_pred[HW_];
    __shared__ unsigned int  s_bitmap[BITWORDS];
    __shared__ float         s_f[NWARPS];
    __shared__ double        s_d[NWARPS];
    __shared__ double        s_d2[NWARPS];
    __shared__ unsigned int  s_u[NWARPS];
    __shared__ unsigned int  s_u2[NWARPS];
    __shared__ unsigned int  s_u3[NWARPS];
    __shared__ unsigned int  s_u4[NWARPS];
    __shared__ unsigned int  s_present;
    __shared__ int           s_last;

    const int b    = blockIdx.x;
    const int tid  = threadIdx.x;
    const int lane = tid & 31;
    const int wid  = tid >> 5;

    if (tid == 0) s_present = 0u;
    __syncthreads();

    const float* pb = pred    + (size_t)b * C_ * HW_;
    const int*   tb = targets + (size_t)b * HW_;
    const int*   ib = inputs  + (size_t)b * HW_;

    float    focal_local = 0.f;
    unsigned eq_local = 0u, cp_local = 0u, pmask = 0u;

#pragma unroll
    for (int i = 0; i < 4; i++) {
        const int g = tid + i * THREADS;               // group of 4 pixels
        float4 v0 = reinterpret_cast<const float4*>(pb)[g];
        int4   tt = reinterpret_cast<const int4*>(tb)[g];
        int4   ii = reinterpret_cast<const int4*>(ib)[g];

        float m[4]  = {v0.x, v0.y, v0.z, v0.w};
        float s[4]  = {1.f, 1.f, 1.f, 1.f};
        float vt[4] = {v0.x, v0.y, v0.z, v0.w};        // valid iff t==0, else overwritten
        int   bi[4] = {0, 0, 0, 0};
        int   t[4]  = {tt.x, tt.y, tt.z, tt.w};
        int   ip[4] = {ii.x, ii.y, ii.z, ii.w};

#pragma unroll
        for (int c = 1; c < C_; c++) {
            float4 v = reinterpret_cast<const float4*>(pb + (size_t)c * HW_)[g];
            float va[4] = {v.x, v.y, v.z, v.w};
#pragma unroll
            for (int j = 0; j < 4; j++) upd(m[j], s[j], bi[j], vt[j], va[j], c, t[j]);
        }

        unsigned char pj[4];
#pragma unroll
        for (int j = 0; j < 4; j++) {
            float ce = m[j] + __logf(s[j]) - vt[j];
            float pt = __expf(-ce);
            float om = 1.f - pt;
            focal_local += om * om * ce;
            eq_local += (bi[j] == t[j]);
            cp_local += (bi[j] == ip[j]);
            pmask |= 1u << t[j];
            pj[j] = (unsigned char)bi[j];
        }
        reinterpret_cast<uchar4*>(s_pred)[g] = make_uchar4(pj[0], pj[1], pj[2], pj[3]);
    }

    // target-color presence mask (per batch)
    pmask = warpOrU(pmask);
    if (lane == 0) atomicOr(&s_present, pmask);

    // creativity: threads [0,128) handle sr[b*128 + tid]
    float creat_local = 0.f;
    if (tid < SRN) {
        float x = sr[(size_t)b * SRN + tid];
        creat_local = __fdividef(1.f, 1.f + __expf(-x));
    }

    // ---- block reductions ----
    float fsum   = warpSumF(focal_local);
    float crsum  = warpSumF(creat_local);
    unsigned es  = warpSumU(eq_local);
    unsigned cs  = warpSumU(cp_local);
    if (lane == 0) { s_f[wid] = fsum; s_d[wid] = (double)crsum; s_u[wid] = es; s_u2[wid] = cs; }
    __syncthreads();

    // ---- diversity: unique 2x2 codes via presence bitmap ----
    for (int k = tid; k < BITWORDS; k += THREADS) s_bitmap[k] = 0u;
    __syncthreads();   // also orders s_pred writes before reads below

    for (int idx = tid; idx < NWIN; idx += THREADS) {
        int h = idx / 63, w = idx - h * 63;
        int base = h * W_ + w;
        int p00 = s_pred[base];
        int p01 = s_pred[base + 1];
        int p10 = s_pred[base + W_];
        int p11 = s_pred[base + W_ + 1];
        int code = p00 * 1000 + p01 * 100 + p10 * 10 + p11;
        atomicOr(&s_bitmap[code >> 5], 1u << (code & 31));
    }
    __syncthreads();

    unsigned cnt = 0u;
    for (int k = tid; k < BITWORDS; k += THREADS) cnt += __popc(s_bitmap[k]);
    cnt = warpSumU(cnt);
    if (lane == 0) s_u3[wid] = cnt;
    __syncthreads();

    // ---- publish per-batch results, detect last block ----
    if (tid == 0) {
        float ft = 0.f; double cr = 0.0;
        unsigned eu = 0u, cu = 0u, un = 0u;
        for (int k = 0; k < NWARPS; k++) {
            ft += s_f[k]; cr += s_d[k]; eu += s_u[k]; cu += s_u2[k]; un += s_u3[k];
        }
        float w = (__popc(s_present) > 3) ? 1.2f : 1.0f;
        a_focal[b] = ft * w;
        a_creat[b] = (float)cr;
        a_eq[b]    = eu;
        a_cp[b]    = cu;
        a_un[b]    = un;
        __threadfence();
        unsigned prev = atomicAdd(&g_count, 1u);
        s_last = (prev == (unsigned)(B_ - 1));
    }
    __syncthreads();
    if (!s_last) return;

    // ================= last block: finalize =================
    if (tid == 0) g_count = 0;     // reset early for next graph replay

    double f = 0.0, cr = 0.0;
    unsigned eq = 0u, st = 0u, cp = 0u, un = 0u;
    for (int k = tid; k < B_; k += THREADS) {
        f  += (double)a_focal[k];
        cr += (double)a_creat[k];
        unsigned e = a_eq[k];
        eq += e;
        st += (e == HW_);
        cp += (a_cp[k] == HW_);
        un += a_un[k];
    }
    f  = warpSumD(f);
    cr = warpSumD(cr);
    eq = warpSumU(eq);
    st = warpSumU(st);
    cp = warpSumU(cp);
    un = warpSumU(un);
    if (lane == 0) {
        s_d[wid] = f; s_d2[wid] = cr;
        s_u[wid] = eq; s_u2[wid] = cp; s_u3[wid] = un; s_u4[wid] = st;
    }
    __syncthreads();

    if (tid == 0) {
        double F = 0.0, CR = 0.0;
        unsigned EQ = 0u, ST = 0u, CP = 0u, UN = 0u;
        for (int k = 0; k < NWARPS; k++) {
            F += s_d[k]; CR += s_d2[k];
            EQ += s_u[k]; ST += s_u4[k]; CP += s_u2[k]; UN += s_u3[k];
        }

        const double NPIX = (double)B_ * (double)HW_;
        double focal       = F / NPIX;
        double iou_mean    = (double)EQ / NPIX;
        double exact_count = 0.2 * (double)ST + 0.8 * ((double)EQ / (double)HW_);
        double comb_mean   = exact_count / (double)B_;
        double exact_bonus = fmax(-comb_mean * 5.0, -3.0);
        double transform_p = ((double)CP / (double)B_) * 0.2;
        double creat       = (CR / ((double)B_ * SRN)) * 0.15;
        double divers      = ((double)UN / (double)NWIN) / (double)B_ * 0.02;
        double grid_bonus  = comb_mean * 0.05;   // grid_size_factor == 1 for 64x64

        double total = focal + transform_p + exact_bonus - creat - divers - grid_bonus;
        if (isnan(total) || isinf(total)) total = fmin(focal, 10.0);

        out[0] = (float)total;
        out[1] = (float)focal;
        out[2] = (float)transform_p;
        out[3] = (float)exact_bonus;
        out[4] = (float)exact_count;
        out[5] = (float)exact_count;   // combined_matches.sum() == exact_count
        out[6] = (float)iou_mean;
        out[7] = (float)creat;
        out[8] = (float)divers;
        out[9] = (float)grid_bonus;
    }
}

// ---------------- launch -----------------------------------------------------
extern "C" void kernel_launch(void* const* d_in, const int* in_sizes, int n_in,
                              void* d_out, int out_size) {
    const float* pred    = (const float*)d_in[0];
    const int*   targets = (const int*)d_in[1];
    const int*   inputs  = (const int*)d_in[2];
    const float* sr      = (const float*)d_in[3];
    float*       out     = (float*)d_out;

    minerva_fused_kernel_r15<<<B_, THREADS>>>(pred, targets, inputs, sr, out);
}

// round 17
// speedup vs baseline: 1.1967x; 1.1532x over previous
// MinervaEnhancedLoss — R17: resubmit of R16 (hash touch only; R16 never ran,
// broker died pre-compile — 7th infra flake; resubmits have always run).
// R9 math + cp.async smem ring (NBUF=8) for pred tiles: LDGSTS holds no regs,
// thread-local wait_group (no barriers), prefetch depth 8 hides ~600cyc DRAM.
#include <cuda_runtime.h>
#include <cstdint>

#define B_    512
#define C_    10
#define HW_   4096          // 64*64
#define W_    64
#define NWIN  3969          // 63*63
#define SRN   128
#define THREADS 256
#define NWARPS  8
#define BITWORDS 313        // ceil(10000/32)
#define NBUF  8             // smem ring depth (tiles of 256x16B = 4KB)
#define NTILE 40            // 4 groups x 10 channels

// ---------------- per-block result arrays (written every run; no init) ------
__device__ float         a_focal[B_];
__device__ float         a_creat[B_];
__device__ unsigned int  a_eq[B_];
__device__ unsigned int  a_cp[B_];
__device__ unsigned int  a_un[B_];
__device__ unsigned int  g_count = 0;

// ---------------- helpers ---------------------------------------------------
__device__ __forceinline__ float warpSumF(float v) {
#pragma unroll
    for (int o = 16; o; o >>= 1) v += __shfl_down_sync(0xffffffffu, v, o);
    return v;
}
__device__ __forceinline__ double warpSumD(double v) {
#pragma unroll
    for (int o = 16; o; o >>= 1) v += __shfl_down_sync(0xffffffffu, v, o);
    return v;
}
__device__ __forceinline__ unsigned warpSumU(unsigned v) {
#pragma unroll
    for (int o = 16; o; o >>= 1) v += __shfl_down_sync(0xffffffffu, v, o);
    return v;
}
__device__ __forceinline__ unsigned warpOrU(unsigned v) {
#pragma unroll
    for (int o = 16; o; o >>= 1) v |= __shfl_down_sync(0xffffffffu, v, o);
    return v;
}

__device__ __forceinline__ uint32_t smem_u32(const void* p) {
    return (uint32_t)__cvta_generic_to_shared(p);
}
__device__ __forceinline__ void cp_async16(uint32_t dst, const void* src) {
    asm volatile("cp.async.cg.shared.global [%0], [%1], 16;\n"
                 :: "r"(dst), "l"(src));
}
__device__ __forceinline__ void cp_commit() {
    asm volatile("cp.async.commit_group;\n");
}
template <int N>
__device__ __forceinline__ void cp_wait() {
    asm volatile("cp.async.wait_group %0;\n" :: "n"(N));
}

// R9-proven online logsumexp + argmax (single-MUFU recurrence). Bit-identical
// to the 32.8us baseline; do NOT touch (R15's SEL rewrite regressed).
__device__ __forceinline__ void upd(float& m, float& s, int& bi, float& vt,
                                    float v, int c, int t) {
    float e  = __expf(-fabsf(v - m));
    bool  gt = (v > m);
    s  = gt ? __fmaf_rn(s, e, 1.0f) : (s + e);
    if (gt) bi = c;                 // strict > keeps FIRST max (jnp.argmax)
    m  = fmaxf(m, v);
    if (c == t) vt = v;
}

// ---------------- single fused kernel ---------------------------------------
__global__ __launch_bounds__(THREADS, 4)
void minerva_fused_kernel_r17(const float* __restrict__ pred,
                              const int*   __restrict__ targets,
                              const int*   __restrict__ inputs,
                              const float* __restrict__ sr,
                              float*       __restrict__ out) {
    __shared__ float4        s_buf[NBUF * THREADS];   // 32 KB ring
    __shared__ unsigned char s_pred[HW_];
    __shared__ unsigned int  s_bitmap[BITWORDS];
    __shared__ float         s_f[NWARPS];
    __shared__ double        s_d[NWARPS];
    __shared__ double        s_d2[NWARPS];
    __shared__ unsigned int  s_u[NWARPS];
    __shared__ unsigned int  s_u2[NWARPS];
    __shared__ unsigned int  s_u3[NWARPS];
    __shared__ unsigned int  s_u4[NWARPS];
    __shared__ unsigned int  s_present;
    __shared__ int           s_last;

    const int b    = blockIdx.x;
    const int tid  = threadIdx.x;
    const int lane = tid & 31;
    const int wid  = tid >> 5;

    if (tid == 0) s_present = 0u;
    __syncthreads();

    const float4* pb4 = reinterpret_cast<const float4*>(pred + (size_t)b * C_ * HW_);
    const int*    tb  = targets + (size_t)b * HW_;
    const int*    ib  = inputs  + (size_t)b * HW_;

    const uint32_t buf_base = smem_u32(s_buf);
    // tile q = g*10 + c  ->  gmem float4 index = c*1024 + g*256 + tid
    //                        smem slot = (q % NBUF)*THREADS + tid

    // ---- prologue: fill the ring ----
#pragma unroll
    for (int q = 0; q < NBUF; q++) {
        const int g = q / C_, c = q - g * C_;
        cp_async16(buf_base + (uint32_t)(((q % NBUF) * THREADS + tid) * 16),
                   pb4 + (c * (HW_ / 4) + g * THREADS + tid));
        cp_commit();
    }

    float    focal_local = 0.f;
    unsigned eq_local = 0u, cp_local = 0u, pmask = 0u;

#pragma unroll
    for (int i = 0; i < 4; i++) {
        const int g = tid + i * THREADS;               // group of 4 pixels
        int4 tt = reinterpret_cast<const int4*>(tb)[g];
        int4 ii = reinterpret_cast<const int4*>(ib)[g];
        int  t[4]  = {tt.x, tt.y, tt.z, tt.w};
        int  ip[4] = {ii.x, ii.y, ii.z, ii.w};

        float m[4], s[4], vt[4];
        int   bi[4];

#pragma unroll
        for (int c = 0; c < C_; c++) {
            const int q = i * C_ + c;
            cp_wait<NBUF - 1>();                        // tile q complete (own copies)
            float4 v = s_buf[(q % NBUF) * THREADS + tid];
            if (q + NBUF < NTILE) {                     // refill the ring
                const int qn = q + NBUF;
                const int gn = qn / C_, cn = qn - gn * C_;
                cp_async16(buf_base + (uint32_t)(((qn % NBUF) * THREADS + tid) * 16),
                           pb4 + (cn * (HW_ / 4) + gn * THREADS + tid));
            }
            cp_commit();                                // keep group count in lockstep
            float va[4] = {v.x, v.y, v.z, v.w};
            if (c == 0) {
#pragma unroll
                for (int j = 0; j < 4; j++) {
                    m[j] = va[j]; s[j] = 1.f; vt[j] = va[j]; bi[j] = 0;
                }
            } else {
#pragma unroll
                for (int j = 0; j < 4; j++) upd(m[j], s[j], bi[j], vt[j], va[j], c, t[j]);
            }
        }

        unsigned char pj[4];
#pragma unroll
        for (int j = 0; j < 4; j++) {
            float ce = m[j] + __logf(s[j]) - vt[j];
            float pt = __expf(-ce);
            float om = 1.f - pt;
            focal_local += om * om * ce;
            eq_local += (bi[j] == t[j]);
            cp_local += (bi[j] == ip[j]);
            pmask |= 1u << t[j];
            pj[j] = (unsigned char)bi[j];
        }
        reinterpret_cast<uchar4*>(s_pred)[g] = make_uchar4(pj[0], pj[1], pj[2], pj[3]);
    }
    cp_wait<0>();   // drain (all consumed; keeps state clean before smem reuse)

    // target-color presence mask (per batch)
    pmask = warpOrU(pmask);
    if (lane == 0) atomicOr(&s_present, pmask);

    // creativity: threads [0,128) handle sr[b*128 + tid]
    float creat_local = 0.f;
    if (tid < SRN) {
        float x = sr[(size_t)b * SRN + tid];
        creat_local = __fdividef(1.f, 1.f + __expf(-x));
    }

    // ---- block reductions ----
    float fsum   = warpSumF(focal_local);
    float crsum  = warpSumF(creat_local);
    unsigned es  = warpSumU(eq_local);
    unsigned cs  = warpSumU(cp_local);
    if (lane == 0) { s_f[wid] = fsum; s_d[wid] = (double)crsum; s_u[wid] = es; s_u2[wid] = cs; }
    __syncthreads();

    // ---- diversity: unique 2x2 codes via presence bitmap ----
    for (int k = tid; k < BITWORDS; k += THREADS) s_bitmap[k] = 0u;
    __syncthreads();   // also orders s_pred writes before reads below

    for (int idx = tid; idx < NWIN; idx += THREADS) {
        int h = idx / 63, w = idx - h * 63;
        int base = h * W_ + w;
        int p00 = s_pred[base];
        int p01 = s_pred[base + 1];
        int p10 = s_pred[base + W_];
        int p11 = s_pred[base + W_ + 1];
        int code = p00 * 1000 + p01 * 100 + p10 * 10 + p11;
        atomicOr(&s_bitmap[code >> 5], 1u << (code & 31));
    }
    __syncthreads();

    unsigned cnt = 0u;
    for (int k = tid; k < BITWORDS; k += THREADS) cnt += __popc(s_bitmap[k]);
    cnt = warpSumU(cnt);
    if (lane == 0) s_u3[wid] = cnt;
    __syncthreads();

    // ---- publish per-batch results, detect last block ----
    if (tid == 0) {
        float ft = 0.f; double cr = 0.0;
        unsigned eu = 0u, cu = 0u, un = 0u;
        for (int k = 0; k < NWARPS; k++) {
            ft += s_f[k]; cr += s_d[k]; eu += s_u[k]; cu += s_u2[k]; un += s_u3[k];
        }
        float w = (__popc(s_present) > 3) ? 1.2f : 1.0f;
        a_focal[b] = ft * w;
        a_creat[b] = (float)cr;
        a_eq[b]    = eu;
        a_cp[b]    = cu;
        a_un[b]    = un;
        __threadfence();
        unsigned prev = atomicAdd(&g_count, 1u);
        s_last = (prev == (unsigned)(B_ - 1));
    }
    __syncthreads();
    if (!s_last) return;

    // ================= last block: finalize =================
    if (tid == 0) g_count = 0;     // reset early for next graph replay

    double f = 0.0, cr = 0.0;
    unsigned eq = 0u, st = 0u, cp = 0u, un = 0u;
    for (int k = tid; k < B_; k += THREADS) {
        f  += (double)a_focal[k];
        cr += (double)a_creat[k];
        unsigned e = a_eq[k];
        eq += e;
        st += (e == HW_);
        cp += (a_cp[k] == HW_);
        un += a_un[k];
    }
    f  = warpSumD(f);
    cr = warpSumD(cr);
    eq = warpSumU(eq);
    st = warpSumU(st);
    cp = warpSumU(cp);
    un = warpSumU(un);
    if (lane == 0) {
        s_d[wid] = f; s_d2[wid] = cr;
        s_u[wid] = eq; s_u2[wid] = cp; s_u3[wid] = un; s_u4[wid] = st;
    }
    __syncthreads();

    if (tid == 0) {
        double F = 0.0, CR = 0.0;
        unsigned EQ = 0u, ST = 0u, CP = 0u, UN = 0u;
        for (int k = 0; k < NWARPS; k++) {
            F += s_d[k]; CR += s_d2[k];
            EQ += s_u[k]; ST += s_u4[k]; CP += s_u2[k]; UN += s_u3[k];
        }

        const double NPIX = (double)B_ * (double)HW_;
        double focal       = F / NPIX;
        double iou_mean    = (double)EQ / NPIX;
        double exact_count = 0.2 * (double)ST + 0.8 * ((double)EQ / (double)HW_);
        double comb_mean   = exact_count / (double)B_;
        double exact_bonus = fmax(-comb_mean * 5.0, -3.0);
        double transform_p = ((double)CP / (double)B_) * 0.2;
        double creat       = (CR / ((double)B_ * SRN)) * 0.15;
        double divers      = ((double)UN / (double)NWIN) / (double)B_ * 0.02;
        double grid_bonus  = comb_mean * 0.05;   // grid_size_factor == 1 for 64x64

        double total = focal + transform_p + exact_bonus - creat - divers - grid_bonus;
        if (isnan(total) || isinf(total)) total = fmin(focal, 10.0);

        out[0] = (float)total;
        out[1] = (float)focal;
        out[2] = (float)transform_p;
        out[3] = (float)exact_bonus;
        out[4] = (float)exact_count;
        out[5] = (float)exact_count;
        out[6] = (float)iou_mean;
        out[7] = (float)creat;
        out[8] = (float)divers;
        out[9] = (float)grid_bonus;
    }
}

// ---------------- launch -----------------------------------------------------
extern "C" void kernel_launch(void* const* d_in, const int* in_sizes, int n_in,
                              void* d_out, int out_size) {
    const float* pred    = (const float*)d_in[0];
    const int*   targets = (const int*)d_in[1];
    const int*   inputs  = (const int*)d_in[2];
    const float* sr      = (const float*)d_in[3];
    float*       out     = (float*)d_out;

    minerva_fused_kernel_r17<<<B_, THREADS>>>(pred, targets, inputs, sr, out);
}